// round 8
// baseline (speedup 1.0000x reference)
#include <cuda_runtime.h>

#define VOCABN 1000
#define EMBN   128
#define HIDN   256
#define G4N    1024   // 4*HID
#define BN     64
#define TN     1024

#define CL     8      // CTAs per cluster
#define GB     4      // batch rows per cluster
#define NTH    1024   // 128 gate rows x 8 k-eighths
#define NQ     8      // k-split factor

// Precomputed per-vocab gate projections: proj[v][g] = emb[v].W_ih[g] + b_ih[g] + b_hh[g]
__device__ float g_proj[VOCABN * G4N];

// ---------------- packed f32x2 helpers ----------------
__device__ __forceinline__ unsigned long long fma2(unsigned long long a,
                                                   unsigned long long b,
                                                   unsigned long long c) {
    unsigned long long d;
    asm("fma.rn.f32x2 %0, %1, %2, %3;" : "=l"(d) : "l"(a), "l"(b), "l"(c));
    return d;
}
__device__ __forceinline__ float lo32(unsigned long long v) {
    return __uint_as_float((unsigned)v);
}
__device__ __forceinline__ float hi32(unsigned long long v) {
    return __uint_as_float((unsigned)(v >> 32));
}

__device__ __forceinline__ float sigf(float x) {
    return __fdividef(1.0f, 1.0f + __expf(-x));
}
__device__ __forceinline__ float tanhf_(float x) {
    return 1.0f - __fdividef(2.0f, __expf(2.0f * x) + 1.0f);
}

// ---------------- cluster smem / mbarrier helpers ----------------
__device__ __forceinline__ unsigned smem_u32(const void* p) {
    return (unsigned)__cvta_generic_to_shared(p);
}
__device__ __forceinline__ void mbar_init(unsigned a, unsigned cnt) {
    asm volatile("mbarrier.init.shared.b64 [%0], %1;" :: "r"(a), "r"(cnt) : "memory");
}
__device__ __forceinline__ unsigned mapa_u32(unsigned a, unsigned rank) {
    unsigned r;
    asm("mapa.shared::cluster.u32 %0, %1, %2;" : "=r"(r) : "r"(a), "r"(rank));
    return r;
}
__device__ __forceinline__ void mbar_arm(unsigned a, unsigned tx_bytes) {
    asm volatile("mbarrier.arrive.expect_tx.shared.b64 _, [%0], %1;"
                 :: "r"(a), "r"(tx_bytes) : "memory");
}
// remote store, counts bytes into the destination CTA's mbarrier
__device__ __forceinline__ void st_async_f32(unsigned dst, float v, unsigned mb) {
    asm volatile(
        "st.async.shared::cluster.mbarrier::complete_tx::bytes.b32 [%0], %1, [%2];"
        :: "r"(dst), "r"(__float_as_uint(v)), "r"(mb) : "memory");
}
__device__ __forceinline__ void mbar_wait(unsigned a, unsigned parity) {
    asm volatile(
        "{\n\t"
        ".reg .pred P;\n\t"
        "mbarrier.try_wait.parity.acquire.cluster.shared::cta.b64 P, [%0], %1;\n\t"
        "@P bra.uni WDONE_%=;\n\t"
        "WLOOP_%=:\n\t"
        "mbarrier.try_wait.parity.acquire.cluster.shared::cta.b64 P, [%0], %1, 0x989680;\n\t"
        "@!P bra.uni WLOOP_%=;\n\t"
        "WDONE_%=:\n\t"
        "}"
        :: "r"(a), "r"(parity) : "memory");
}
__device__ __forceinline__ void cluster_sync_once() {
    asm volatile("barrier.cluster.arrive.aligned;" ::: "memory");
    asm volatile("barrier.cluster.wait.aligned;" ::: "memory");
}

// ---------------------------------------------------------------------------
// Kernel 1: vocab projection table. 125 blocks x 256 threads, 8 vocab/block.
// ---------------------------------------------------------------------------
__global__ void __launch_bounds__(256) proj_kernel(
    const float* __restrict__ emb, const float* __restrict__ W_ih,
    const float* __restrict__ b_ih, const float* __restrict__ b_hh)
{
    __shared__ float4 es4[8][EMBN / 4];
    const int v0 = blockIdx.x * 8;
    const int tid = threadIdx.x;
    for (int i = tid; i < 8 * EMBN; i += 256) {
        int v = i >> 7, e = i & 127;
        ((float*)es4)[v * EMBN + e] = emb[(v0 + v) * EMBN + e];
    }
    __syncthreads();

    const float4* W4 = (const float4*)W_ih;
#pragma unroll
    for (int rr = 0; rr < 4; rr++) {
        int g = tid + rr * 256;
        float acc[8];
#pragma unroll
        for (int v = 0; v < 8; v++) acc[v] = 0.f;
        for (int e4 = 0; e4 < EMBN / 4; e4++) {
            float4 w = W4[g * (EMBN / 4) + e4];
#pragma unroll
            for (int v = 0; v < 8; v++) {
                float4 x = es4[v][e4];
                acc[v] += w.x * x.x + w.y * x.y + w.z * x.z + w.w * x.w;
            }
        }
        float bias = b_ih[g] + b_hh[g];
#pragma unroll
        for (int v = 0; v < 8; v++)
            g_proj[(v0 + v) * G4N + g] = acc[v] + bias;
    }
}

// ---------------------------------------------------------------------------
// Kernel 2: recurrence. 16 clusters x 8 CTAs; cluster owns 4 batch rows.
// Thread = (gate row lr in 0..127, k-eighth q in 0..7). Each thread keeps its
// 32 W_hh floats in 16 u64 registers — zero per-step W traffic, 32 warps/SM
// for latency hiding. psum[8 eighths] reduced by the cell threads inside the
// single barrier. h exchange: st.async + double-buffered tx mbarriers.
// ---------------------------------------------------------------------------
__global__ void __launch_bounds__(NTH, 1) __cluster_dims__(CL, 1, 1)
lstm_kernel(const int* __restrict__ tokens, const int* __restrict__ lengths,
            const float* __restrict__ W_hh, float* __restrict__ out)
{
    __shared__ float hb[2][GB][HIDN];          // 8 KB: double-buffered h, batch-major
    __shared__ float psum[NQ][GB][128];        // 16 KB: [eighth][batch][gate-row]
    __shared__ __align__(8) unsigned long long mbar[2];

    const int rank = blockIdx.x;               // 0..7
    const int cid  = blockIdx.y;               // 0..15
    const int tid  = threadIdx.x;
    const int lr   = tid & 127;                // gate row 0..127
    const int q    = tid >> 7;                 // k-eighth 0..7
    const int base = rank * 32;
    const int b0   = cid * GB;
    const unsigned TXB = 4096;                 // bytes per exchange phase
    const int grow = (lr >> 5) * HIDN + base + (lr & 31);  // my W_hh row

    // --- W slice into registers: 32 floats (k-eighth of a row) = 16 pairs ---
    unsigned long long wpair[16];
    {
        const ulonglong2* wr =
            (const ulonglong2*)(W_hh + (size_t)grow * HIDN + q * 32);
#pragma unroll
        for (int j = 0; j < 8; j++) {
            ulonglong2 v = wr[j];
            wpair[2 * j]     = v.x;
            wpair[2 * j + 1] = v.y;
        }
    }

    const unsigned mb0 = smem_u32(&mbar[0]);
    const unsigned mb1 = smem_u32(&mbar[1]);
    if (tid == 0) {
        mbar_init(mb0, 1);
        mbar_init(mb1, 1);
        mbar_arm(mb1, TXB);    // pre-arm for t=1 data (arrives into hb[1])
    }
    for (int i = tid; i < GB * HIDN; i += NTH) ((float*)hb[0])[i] = 0.f;
    __syncthreads();
    cluster_sync_once();       // init + hb[0]=0 visible cluster-wide before any push

    // cell identity (tid<256): lane pairs (2j,2j+1) share one (h,batch)
    const int pr = tid >> 1;        // 0..127 (for tid<256)
    const int s  = tid & 1;         // 0 -> {i,f}, 1 -> {g,o}
    const int hl = pr & 31;
    const int bb = pr >> 5;
    const int mylen = (tid < 256) ? lengths[b0 + bb] : 0;

    const int len0 = lengths[b0 + 0];
    const int len1 = lengths[b0 + 1];
    const int len2 = lengths[b0 + 2];
    const int len3 = lengths[b0 + 3];
    int steps = max(max(len0, len1), max(len2, len3));
    if (steps > TN) steps = TN;

    // input projections live in the q==0 threads (tid<128, one per gate row)
    float xw0 = 0.f, xw1 = 0.f, xw2 = 0.f, xw3 = 0.f;
    if (q == 0) {
        xw0 = g_proj[tokens[(b0 + 0) * TN] * G4N + grow];
        xw1 = g_proj[tokens[(b0 + 1) * TN] * G4N + grow];
        xw2 = g_proj[tokens[(b0 + 2) * TN] * G4N + grow];
        xw3 = g_proj[tokens[(b0 + 3) * TN] * G4N + grow];
    }

    float creg = 0.f, hreg = 0.f;
    unsigned ph0 = 0, ph1 = 0;

    for (int t = 0; t < steps; t++) {
        const int buf = t & 1;
        // wait for h(t) (skip t=0: hb[0] prezeroed), then re-arm this barrier
        // for the phase two steps ahead.
        if (t) {
            if (buf) { mbar_wait(mb1, ph1); ph1 ^= 1; }
            else     { mbar_wait(mb0, ph0); ph0 ^= 1; }
        }
        if (tid == 0) mbar_arm(buf ? mb1 : mb0, TXB);

        // prefetch next step's input projection (L2 latency hidden by matvec)
        float xn0, xn1, xn2, xn3;
        if (q == 0) {
            int tn = min(t + 1, TN - 1);
            xn0 = g_proj[tokens[(b0 + 0) * TN + tn] * G4N + grow];
            xn1 = g_proj[tokens[(b0 + 1) * TN + tn] * G4N + grow];
            xn2 = g_proj[tokens[(b0 + 2) * TN + tn] * G4N + grow];
            xn3 = g_proj[tokens[(b0 + 3) * TN + tn] * G4N + grow];
        }

        // packed matvec: my gate row, my k-eighth, 4 batches.
        // W from registers; h via warp-uniform broadcast LDS.128.
        const float* h0p = hb[buf][0] + q * 32;
        const float* h1p = hb[buf][1] + q * 32;
        const float* h2p = hb[buf][2] + q * 32;
        const float* h3p = hb[buf][3] + q * 32;
        unsigned long long a0 = 0ull, a1 = 0ull, a2 = 0ull, a3 = 0ull;
#pragma unroll
        for (int c = 0; c < 8; c++) {
            ulonglong2 h0 = *(const ulonglong2*)(h0p + c * 4);
            ulonglong2 h1 = *(const ulonglong2*)(h1p + c * 4);
            ulonglong2 h2 = *(const ulonglong2*)(h2p + c * 4);
            ulonglong2 h3 = *(const ulonglong2*)(h3p + c * 4);
            a0 = fma2(wpair[2 * c], h0.x, a0);
            a1 = fma2(wpair[2 * c], h1.x, a1);
            a2 = fma2(wpair[2 * c], h2.x, a2);
            a3 = fma2(wpair[2 * c], h3.x, a3);
            a0 = fma2(wpair[2 * c + 1], h0.y, a0);
            a1 = fma2(wpair[2 * c + 1], h1.y, a1);
            a2 = fma2(wpair[2 * c + 1], h2.y, a2);
            a3 = fma2(wpair[2 * c + 1], h3.y, a3);
        }
        // pair-summed scalar partials; eighth 0 folds in the input projection
        if (q == 0) {
            psum[0][0][lr] = lo32(a0) + hi32(a0) + xw0;
            psum[0][1][lr] = lo32(a1) + hi32(a1) + xw1;
            psum[0][2][lr] = lo32(a2) + hi32(a2) + xw2;
            psum[0][3][lr] = lo32(a3) + hi32(a3) + xw3;
            xw0 = xn0; xw1 = xn1; xw2 = xn2; xw3 = xn3;
        } else {
            psum[q][0][lr] = lo32(a0) + hi32(a0);
            psum[q][1][lr] = lo32(a1) + hi32(a1);
            psum[q][2][lr] = lo32(a2) + hi32(a2);
            psum[q][3][lr] = lo32(a3) + hi32(a3);
        }
        __syncthreads();

        // cell update on tid<256: lane pair (s=0: sig(i),sig(f); s=1: tanh(g),sig(o))
        if (tid < 256) {
            const int r0 = (s ? 64 : 0) + hl;
            const int r1 = (s ? 96 : 32) + hl;
            float gA = ((psum[0][bb][r0] + psum[1][bb][r0]) +
                        (psum[2][bb][r0] + psum[3][bb][r0])) +
                       ((psum[4][bb][r0] + psum[5][bb][r0]) +
                        (psum[6][bb][r0] + psum[7][bb][r0]));
            float gB = ((psum[0][bb][r1] + psum[1][bb][r1]) +
                        (psum[2][bb][r1] + psum[3][bb][r1])) +
                       ((psum[4][bb][r1] + psum[5][bb][r1]) +
                        (psum[6][bb][r1] + psum[7][bb][r1]));
            float u = s ? tanhf_(gA) : sigf(gA);
            float v = sigf(gB);
            float ou = __shfl_xor_sync(0xffffffffu, u, 1);
            float ov = __shfl_xor_sync(0xffffffffu, v, 1);
            float i_ = s ? ou : u;
            float f_ = s ? ov : v;
            float g_ = s ? u  : ou;
            float o_ = s ? v  : ov;
            float cn = f_ * creg + i_ * g_;
            float hn = o_ * tanhf_(cn);
            if (t < mylen) { creg = cn; hreg = hn; }

            if (t + 1 < steps) {
                // fire-and-forget: remote stores carry their own completion
                const int nb = buf ^ 1;
                const unsigned dloc = smem_u32(&hb[nb][bb][base + hl]);
                const unsigned mloc = nb ? mb1 : mb0;
#pragma unroll
                for (int r = 0; r < 4; r++) {
                    const unsigned rk = 4 * s + r;
                    st_async_f32(mapa_u32(dloc, rk), hreg, mapa_u32(mloc, rk));
                }
            }
        }
    }

    if (tid < 256 && s == 0)
        out[(b0 + bb) * HIDN + base + hl] = hreg;
}

// ---------------------------------------------------------------------------
extern "C" void kernel_launch(void* const* d_in, const int* in_sizes, int n_in,
                              void* d_out, int out_size)
{
    const int*   tokens  = (const int*)d_in[0];
    const int*   lengths = (const int*)d_in[1];
    const float* emb     = (const float*)d_in[2];
    const float* W_ih    = (const float*)d_in[3];
    const float* W_hh    = (const float*)d_in[4];
    const float* b_ih    = (const float*)d_in[5];
    const float* b_hh    = (const float*)d_in[6];
    float* out = (float*)d_out;

    proj_kernel<<<VOCABN / 8, 256>>>(emb, W_ih, b_ih, b_hh);

    dim3 grid(CL, BN / GB);
    lstm_kernel<<<grid, NTH>>>(tokens, lengths, W_hh, out);
}

// round 9
// speedup vs baseline: 1.1163x; 1.1163x over previous
#include <cuda_runtime.h>

#define VOCABN 1000
#define EMBN   128
#define HIDN   256
#define G4N    1024   // 4*HID
#define BN     64
#define TN     1024

#define CL     8      // CTAs per cluster
#define GB     4      // batch rows per cluster
#define NTH    512    // 128 gate rows x 4 k-quarters

// Precomputed per-vocab gate projections: proj[v][g] = emb[v].W_ih[g] + b_ih[g] + b_hh[g]
__device__ float g_proj[VOCABN * G4N];

// ---------------- packed f32x2 helpers ----------------
__device__ __forceinline__ unsigned long long fma2(unsigned long long a,
                                                   unsigned long long b,
                                                   unsigned long long c) {
    unsigned long long d;
    asm("fma.rn.f32x2 %0, %1, %2, %3;" : "=l"(d) : "l"(a), "l"(b), "l"(c));
    return d;
}
__device__ __forceinline__ float lo32(unsigned long long v) {
    return __uint_as_float((unsigned)v);
}
__device__ __forceinline__ float hi32(unsigned long long v) {
    return __uint_as_float((unsigned)(v >> 32));
}

__device__ __forceinline__ float sigf(float x) {
    return __fdividef(1.0f, 1.0f + __expf(-x));
}
__device__ __forceinline__ float tanhf_(float x) {
    return 1.0f - __fdividef(2.0f, __expf(2.0f * x) + 1.0f);
}

// ---------------- cluster smem / mbarrier helpers ----------------
__device__ __forceinline__ unsigned smem_u32(const void* p) {
    return (unsigned)__cvta_generic_to_shared(p);
}
__device__ __forceinline__ void mbar_init(unsigned a, unsigned cnt) {
    asm volatile("mbarrier.init.shared.b64 [%0], %1;" :: "r"(a), "r"(cnt) : "memory");
}
__device__ __forceinline__ unsigned mapa_u32(unsigned a, unsigned rank) {
    unsigned r;
    asm("mapa.shared::cluster.u32 %0, %1, %2;" : "=r"(r) : "r"(a), "r"(rank));
    return r;
}
__device__ __forceinline__ void mbar_arm(unsigned a, unsigned tx_bytes) {
    asm volatile("mbarrier.arrive.expect_tx.shared.b64 _, [%0], %1;"
                 :: "r"(a), "r"(tx_bytes) : "memory");
}
// remote store, counts bytes into the destination CTA's mbarrier
__device__ __forceinline__ void st_async_f32(unsigned dst, float v, unsigned mb) {
    asm volatile(
        "st.async.shared::cluster.mbarrier::complete_tx::bytes.b32 [%0], %1, [%2];"
        :: "r"(dst), "r"(__float_as_uint(v)), "r"(mb) : "memory");
}
__device__ __forceinline__ void mbar_wait(unsigned a, unsigned parity) {
    asm volatile(
        "{\n\t"
        ".reg .pred P;\n\t"
        "mbarrier.try_wait.parity.acquire.cluster.shared::cta.b64 P, [%0], %1;\n\t"
        "@P bra.uni WDONE_%=;\n\t"
        "WLOOP_%=:\n\t"
        "mbarrier.try_wait.parity.acquire.cluster.shared::cta.b64 P, [%0], %1, 0x989680;\n\t"
        "@!P bra.uni WLOOP_%=;\n\t"
        "WDONE_%=:\n\t"
        "}"
        :: "r"(a), "r"(parity) : "memory");
}
__device__ __forceinline__ void cluster_sync_once() {
    asm volatile("barrier.cluster.arrive.aligned;" ::: "memory");
    asm volatile("barrier.cluster.wait.aligned;" ::: "memory");
}

// ---------------------------------------------------------------------------
// Kernel 1: vocab projection table. 125 blocks x 256 threads, 8 vocab/block.
// ---------------------------------------------------------------------------
__global__ void __launch_bounds__(256) proj_kernel(
    const float* __restrict__ emb, const float* __restrict__ W_ih,
    const float* __restrict__ b_ih, const float* __restrict__ b_hh)
{
    __shared__ float4 es4[8][EMBN / 4];
    const int v0 = blockIdx.x * 8;
    const int tid = threadIdx.x;
    for (int i = tid; i < 8 * EMBN; i += 256) {
        int v = i >> 7, e = i & 127;
        ((float*)es4)[v * EMBN + e] = emb[(v0 + v) * EMBN + e];
    }
    __syncthreads();

    const float4* W4 = (const float4*)W_ih;
#pragma unroll
    for (int rr = 0; rr < 4; rr++) {
        int g = tid + rr * 256;
        float acc[8];
#pragma unroll
        for (int v = 0; v < 8; v++) acc[v] = 0.f;
        for (int e4 = 0; e4 < EMBN / 4; e4++) {
            float4 w = W4[g * (EMBN / 4) + e4];
#pragma unroll
            for (int v = 0; v < 8; v++) {
                float4 x = es4[v][e4];
                acc[v] += w.x * x.x + w.y * x.y + w.z * x.z + w.w * x.w;
            }
        }
        float bias = b_ih[g] + b_hh[g];
#pragma unroll
        for (int v = 0; v < 8; v++)
            g_proj[(v0 + v) * G4N + g] = acc[v] + bias;
    }
}

// ---------------------------------------------------------------------------
// Kernel 2: recurrence. 16 clusters x 8 CTAs; cluster owns 4 batch rows.
// Thread = (gate row lr, k-quarter q). W_hh k-quarter of one gate row in
// registers (32 u64). Quarter q's h chunk k in [64q,64q+64) is produced by
// EXACTLY ranks 2q and 2q+1 -> per-quarter tx mbarriers (1024 B each):
// a quarter starts its matvec as soon as ITS producers' data lands, and
// quarters 2..3 run step t+1's wait+matvec while quarters 0..1 still do
// step t's cell + pushes (psum double-buffered; barrier phases can't alias
// because reaching barrier(t+1) transitively requires barrier(t) released).
// ---------------------------------------------------------------------------
__global__ void __launch_bounds__(NTH, 1) __cluster_dims__(CL, 1, 1)
lstm_kernel(const int* __restrict__ tokens, const int* __restrict__ lengths,
            const float* __restrict__ W_hh, float* __restrict__ out)
{
    __shared__ float hb[2][GB][HIDN];          // 8 KB: double-buffered h, batch-major
    __shared__ float psum[2][4][GB][128];      // 16 KB: [buf][quarter][batch][row]
    __shared__ __align__(8) unsigned long long mbar[2][4];  // [buf][quarter]

    const int rank = blockIdx.x;               // 0..7
    const int cid  = blockIdx.y;               // 0..15
    const int tid  = threadIdx.x;
    const int lr   = tid & 127;                // gate row 0..127
    const int q    = tid >> 7;                 // k-quarter 0..3
    const int base = rank * 32;
    const int b0   = cid * GB;
    const unsigned TXQ = 1024;                 // bytes per quarter-barrier phase
    const int grow = (lr >> 5) * HIDN + base + (lr & 31);  // my W_hh row

    // --- W slice into registers: 64 floats (k-quarter of a row) = 32 pairs ---
    unsigned long long wpair[32];
    {
        const ulonglong2* wr =
            (const ulonglong2*)(W_hh + (size_t)grow * HIDN + q * 64);
#pragma unroll
        for (int j = 0; j < 16; j++) {
            ulonglong2 v = wr[j];
            wpair[2 * j]     = v.x;
            wpair[2 * j + 1] = v.y;
        }
    }

    const unsigned mybar0 = smem_u32(&mbar[0][q]);
    const unsigned mybar1 = smem_u32(&mbar[1][q]);
    if (tid < 8) {
        mbar_init(smem_u32(&mbar[tid >> 2][tid & 3]), 1);
        if (tid >> 2) mbar_arm(smem_u32(&mbar[1][tid & 3]), TXQ);  // pre-arm t=1
    }
    for (int i = tid; i < GB * HIDN; i += NTH) ((float*)hb[0])[i] = 0.f;
    __syncthreads();
    cluster_sync_once();       // init + hb[0]=0 visible cluster-wide before any push

    // cell identity (tid<256): lane pairs (2j,2j+1) share one (h,batch)
    const int pr = tid >> 1;        // 0..127 (for tid<256)
    const int s  = tid & 1;         // 0 -> {i,f}, 1 -> {g,o}
    const int hl = pr & 31;
    const int bb = pr >> 5;
    const int mylen = (tid < 256) ? lengths[b0 + bb] : 0;

    const int len0 = lengths[b0 + 0];
    const int len1 = lengths[b0 + 1];
    const int len2 = lengths[b0 + 2];
    const int len3 = lengths[b0 + 3];
    int steps = max(max(len0, len1), max(len2, len3));
    if (steps > TN) steps = TN;

    // input projections live in the q==0 threads (tid<128, one per gate row)
    float xw0 = 0.f, xw1 = 0.f, xw2 = 0.f, xw3 = 0.f;
    if (q == 0) {
        xw0 = g_proj[tokens[(b0 + 0) * TN] * G4N + grow];
        xw1 = g_proj[tokens[(b0 + 1) * TN] * G4N + grow];
        xw2 = g_proj[tokens[(b0 + 2) * TN] * G4N + grow];
        xw3 = g_proj[tokens[(b0 + 3) * TN] * G4N + grow];
    }

    float creg = 0.f, hreg = 0.f;
    unsigned ph0 = 0, ph1 = 0;

    for (int t = 0; t < steps; t++) {
        const int buf = t & 1;
        // wait ONLY for my quarter's producers (ranks 2q, 2q+1); skip t=0.
        if (t) {
            if (buf) { mbar_wait(mybar1, ph1); ph1 ^= 1; }
            else     { mbar_wait(mybar0, ph0); ph0 ^= 1; }
        }
        // re-arm my quarter's barrier for step t+2 (one thread per quarter)
        if (lr == 0) mbar_arm(buf ? mybar1 : mybar0, TXQ);

        // prefetch next step's input projection (L2 latency hidden by matvec)
        float xn0, xn1, xn2, xn3;
        if (q == 0) {
            int tn = min(t + 1, TN - 1);
            xn0 = g_proj[tokens[(b0 + 0) * TN + tn] * G4N + grow];
            xn1 = g_proj[tokens[(b0 + 1) * TN + tn] * G4N + grow];
            xn2 = g_proj[tokens[(b0 + 2) * TN + tn] * G4N + grow];
            xn3 = g_proj[tokens[(b0 + 3) * TN + tn] * G4N + grow];
        }

        // packed matvec: my gate row, my k-quarter, 4 batches.
        const float* h0p = hb[buf][0] + q * 64;
        const float* h1p = hb[buf][1] + q * 64;
        const float* h2p = hb[buf][2] + q * 64;
        const float* h3p = hb[buf][3] + q * 64;
        unsigned long long a0 = 0ull, a1 = 0ull, a2 = 0ull, a3 = 0ull;
#pragma unroll
        for (int c = 0; c < 16; c++) {
            ulonglong2 h0 = *(const ulonglong2*)(h0p + c * 4);
            ulonglong2 h1 = *(const ulonglong2*)(h1p + c * 4);
            ulonglong2 h2 = *(const ulonglong2*)(h2p + c * 4);
            ulonglong2 h3 = *(const ulonglong2*)(h3p + c * 4);
            a0 = fma2(wpair[2 * c], h0.x, a0);
            a1 = fma2(wpair[2 * c], h1.x, a1);
            a2 = fma2(wpair[2 * c], h2.x, a2);
            a3 = fma2(wpair[2 * c], h3.x, a3);
            a0 = fma2(wpair[2 * c + 1], h0.y, a0);
            a1 = fma2(wpair[2 * c + 1], h1.y, a1);
            a2 = fma2(wpair[2 * c + 1], h2.y, a2);
            a3 = fma2(wpair[2 * c + 1], h3.y, a3);
        }
        // pair-summed scalar partials into the double-buffered psum
        if (q == 0) {
            psum[buf][0][0][lr] = lo32(a0) + hi32(a0) + xw0;
            psum[buf][0][1][lr] = lo32(a1) + hi32(a1) + xw1;
            psum[buf][0][2][lr] = lo32(a2) + hi32(a2) + xw2;
            psum[buf][0][3][lr] = lo32(a3) + hi32(a3) + xw3;
            xw0 = xn0; xw1 = xn1; xw2 = xn2; xw3 = xn3;
        } else {
            psum[buf][q][0][lr] = lo32(a0) + hi32(a0);
            psum[buf][q][1][lr] = lo32(a1) + hi32(a1);
            psum[buf][q][2][lr] = lo32(a2) + hi32(a2);
            psum[buf][q][3][lr] = lo32(a3) + hi32(a3);
        }
        __syncthreads();

        // cell update on tid<256; quarters 2..3 fall through to step t+1 now.
        if (tid < 256) {
            const int r0 = (s ? 64 : 0) + hl;
            const int r1 = (s ? 96 : 32) + hl;
            float gA = (psum[buf][0][bb][r0] + psum[buf][1][bb][r0]) +
                       (psum[buf][2][bb][r0] + psum[buf][3][bb][r0]);
            float gB = (psum[buf][0][bb][r1] + psum[buf][1][bb][r1]) +
                       (psum[buf][2][bb][r1] + psum[buf][3][bb][r1]);
            float u = s ? tanhf_(gA) : sigf(gA);
            float v = sigf(gB);
            float ou = __shfl_xor_sync(0xffffffffu, u, 1);
            float ov = __shfl_xor_sync(0xffffffffu, v, 1);
            float i_ = s ? ou : u;
            float f_ = s ? ov : v;
            float g_ = s ? u  : ou;
            float o_ = s ? v  : ov;
            float cn = f_ * creg + i_ * g_;
            float hn = o_ * tanhf_(cn);
            if (t < mylen) { creg = cn; hreg = hn; }

            if (t + 1 < steps) {
                // push to all 8 CTAs (4 each lane of the pair), signaling the
                // destination's per-quarter barrier for MY k-range (rank>>1).
                const int nb = buf ^ 1;
                const unsigned dloc = smem_u32(&hb[nb][bb][base + hl]);
                const unsigned mloc = smem_u32(&mbar[nb][rank >> 1]);
#pragma unroll
                for (int r = 0; r < 4; r++) {
                    const unsigned rk = 4 * s + r;
                    st_async_f32(mapa_u32(dloc, rk), hreg, mapa_u32(mloc, rk));
                }
            }
        }
    }

    if (tid < 256 && s == 0)
        out[(b0 + bb) * HIDN + base + hl] = hreg;
}

// ---------------------------------------------------------------------------
extern "C" void kernel_launch(void* const* d_in, const int* in_sizes, int n_in,
                              void* d_out, int out_size)
{
    const int*   tokens  = (const int*)d_in[0];
    const int*   lengths = (const int*)d_in[1];
    const float* emb     = (const float*)d_in[2];
    const float* W_ih    = (const float*)d_in[3];
    const float* W_hh    = (const float*)d_in[4];
    const float* b_ih    = (const float*)d_in[5];
    const float* b_hh    = (const float*)d_in[6];
    float* out = (float*)d_out;

    proj_kernel<<<VOCABN / 8, 256>>>(emb, W_ih, b_ih, b_hh);

    dim3 grid(CL, BN / GB);
    lstm_kernel<<<grid, NTH>>>(tokens, lengths, W_hh, out);
}

// round 10
// speedup vs baseline: 1.1446x; 1.0254x over previous
#include <cuda_runtime.h>

#define VOCABN 1000
#define EMBN   128
#define HIDN   256
#define G4N    1024   // 4*HID
#define BN     64
#define TN     1024

#define CL     8      // CTAs per cluster
#define NTH    512    // 128 gate rows x 4 k-quarters

// Precomputed per-vocab gate projections: proj[v][g] = emb[v].W_ih[g] + b_ih[g] + b_hh[g]
__device__ float g_proj[VOCABN * G4N];

// ---------------- packed f32x2 helpers ----------------
__device__ __forceinline__ unsigned long long fma2(unsigned long long a,
                                                   unsigned long long b,
                                                   unsigned long long c) {
    unsigned long long d;
    asm("fma.rn.f32x2 %0, %1, %2, %3;" : "=l"(d) : "l"(a), "l"(b), "l"(c));
    return d;
}
__device__ __forceinline__ float lo32(unsigned long long v) {
    return __uint_as_float((unsigned)v);
}
__device__ __forceinline__ float hi32(unsigned long long v) {
    return __uint_as_float((unsigned)(v >> 32));
}

__device__ __forceinline__ float sigf(float x) {
    return __fdividef(1.0f, 1.0f + __expf(-x));
}
__device__ __forceinline__ float tanhf_(float x) {
    return 1.0f - __fdividef(2.0f, __expf(2.0f * x) + 1.0f);
}

// ---------------- cluster smem / mbarrier helpers ----------------
__device__ __forceinline__ unsigned smem_u32(const void* p) {
    return (unsigned)__cvta_generic_to_shared(p);
}
__device__ __forceinline__ void mbar_init(unsigned a, unsigned cnt) {
    asm volatile("mbarrier.init.shared.b64 [%0], %1;" :: "r"(a), "r"(cnt) : "memory");
}
__device__ __forceinline__ unsigned mapa_u32(unsigned a, unsigned rank) {
    unsigned r;
    asm("mapa.shared::cluster.u32 %0, %1, %2;" : "=r"(r) : "r"(a), "r"(rank));
    return r;
}
__device__ __forceinline__ void mbar_arm(unsigned a, unsigned tx_bytes) {
    asm volatile("mbarrier.arrive.expect_tx.shared.b64 _, [%0], %1;"
                 :: "r"(a), "r"(tx_bytes) : "memory");
}
// remote store, counts bytes into the destination CTA's mbarrier
__device__ __forceinline__ void st_async_f32(unsigned dst, float v, unsigned mb) {
    asm volatile(
        "st.async.shared::cluster.mbarrier::complete_tx::bytes.b32 [%0], %1, [%2];"
        :: "r"(dst), "r"(__float_as_uint(v)), "r"(mb) : "memory");
}
__device__ __forceinline__ void mbar_wait(unsigned a, unsigned parity) {
    asm volatile(
        "{\n\t"
        ".reg .pred P;\n\t"
        "mbarrier.try_wait.parity.acquire.cluster.shared::cta.b64 P, [%0], %1;\n\t"
        "@P bra.uni WDONE_%=;\n\t"
        "WLOOP_%=:\n\t"
        "mbarrier.try_wait.parity.acquire.cluster.shared::cta.b64 P, [%0], %1, 0x989680;\n\t"
        "@!P bra.uni WLOOP_%=;\n\t"
        "WDONE_%=:\n\t"
        "}"
        :: "r"(a), "r"(parity) : "memory");
}
__device__ __forceinline__ void cluster_sync_once() {
    asm volatile("barrier.cluster.arrive.aligned;" ::: "memory");
    asm volatile("barrier.cluster.wait.aligned;" ::: "memory");
}

// ---------------------------------------------------------------------------
// Kernel 1: vocab projection table. 125 blocks x 256 threads, 8 vocab/block.
// ---------------------------------------------------------------------------
__global__ void __launch_bounds__(256) proj_kernel(
    const float* __restrict__ emb, const float* __restrict__ W_ih,
    const float* __restrict__ b_ih, const float* __restrict__ b_hh)
{
    __shared__ float4 es4[8][EMBN / 4];
    const int v0 = blockIdx.x * 8;
    const int tid = threadIdx.x;
    for (int i = tid; i < 8 * EMBN; i += 256) {
        int v = i >> 7, e = i & 127;
        ((float*)es4)[v * EMBN + e] = emb[(v0 + v) * EMBN + e];
    }
    __syncthreads();

    const float4* W4 = (const float4*)W_ih;
#pragma unroll
    for (int rr = 0; rr < 4; rr++) {
        int g = tid + rr * 256;
        float acc[8];
#pragma unroll
        for (int v = 0; v < 8; v++) acc[v] = 0.f;
        for (int e4 = 0; e4 < EMBN / 4; e4++) {
            float4 w = W4[g * (EMBN / 4) + e4];
#pragma unroll
            for (int v = 0; v < 8; v++) {
                float4 x = es4[v][e4];
                acc[v] += w.x * x.x + w.y * x.y + w.z * x.z + w.w * x.w;
            }
        }
        float bias = b_ih[g] + b_hh[g];
#pragma unroll
        for (int v = 0; v < 8; v++)
            g_proj[(v0 + v) * G4N + g] = acc[v] + bias;
    }
}

// ---------------------------------------------------------------------------
// Kernel 2: recurrence. 16 clusters x 8 CTAs; cluster owns 4 batch rows as
// TWO independent groups of 2, time-interleaved: while group g is in its
// exchange window (cell -> st.async push -> DSMEM delivery -> wait), all 16
// warps compute group g^1's matvec. Exchange latency hides behind compute.
// W_hh k-quarter of one gate row per thread in registers (32 u64).
// ---------------------------------------------------------------------------
__global__ void __launch_bounds__(NTH, 1) __cluster_dims__(CL, 1, 1)
lstm_kernel(const int* __restrict__ tokens, const int* __restrict__ lengths,
            const float* __restrict__ W_hh, float* __restrict__ out)
{
    __shared__ float hb[2][2][2][HIDN];        // 8 KB: [group][buf][batch][k]
    __shared__ float psum[2][4][2][128];       // 8 KB: [group][quarter][batch][row]
    __shared__ __align__(8) unsigned long long mbar[2][2];  // [group][buf]

    const int rank = blockIdx.x;               // 0..7
    const int cid  = blockIdx.y;               // 0..15
    const int tid  = threadIdx.x;
    const int lr   = tid & 127;                // gate row 0..127
    const int q    = tid >> 7;                 // k-quarter 0..3
    const int base = rank * 32;
    const int b0   = cid * 4;
    const unsigned TXB = 2048;                 // 8 ranks x 32 h x 2 batches x 4B
    const int grow = (lr >> 5) * HIDN + base + (lr & 31);  // my W_hh row

    // --- W slice into registers: 64 floats (k-quarter of a row) = 32 pairs ---
    unsigned long long wpair[32];
    {
        const ulonglong2* wr =
            (const ulonglong2*)(W_hh + (size_t)grow * HIDN + q * 64);
#pragma unroll
        for (int j = 0; j < 16; j++) {
            ulonglong2 v = wr[j];
            wpair[2 * j]     = v.x;
            wpair[2 * j + 1] = v.y;
        }
    }

    if (tid < 4) mbar_init(smem_u32(&mbar[tid >> 1][tid & 1]), 1);
    if (tid < 2) mbar_arm(smem_u32(&mbar[tid][1]), TXB);   // pre-arm t=1 phases
    for (int i = tid; i < 2 * 2 * 2 * HIDN; i += NTH) ((float*)hb)[i] = 0.f;
    __syncthreads();
    cluster_sync_once();       // init + zeros visible cluster-wide before any push

    // cell identity (tid<128): lane pairs (2j,2j+1) share one (h,batch)
    const int pr = tid >> 1;        // 0..63 (for tid<128)
    const int s  = tid & 1;         // 0 -> {i,f}, 1 -> {g,o}
    const int hl = pr & 31;
    const int bb = pr >> 5;         // 0..1 within group
    int mylen[2] = {0, 0};
    if (tid < 128) {
        mylen[0] = lengths[b0 + 0 + bb];
        mylen[1] = lengths[b0 + 2 + bb];
    }

    const int len0 = lengths[b0 + 0];
    const int len1 = lengths[b0 + 1];
    const int len2 = lengths[b0 + 2];
    const int len3 = lengths[b0 + 3];
    int steps = max(max(len0, len1), max(len2, len3));
    if (steps > TN) steps = TN;

    // input projections live in the q==0 threads (tid<128, one per gate row)
    float xw[2][2];
    if (q == 0) {
#pragma unroll
        for (int g = 0; g < 2; g++) {
            xw[g][0] = g_proj[tokens[(b0 + 2 * g + 0) * TN] * G4N + grow];
            xw[g][1] = g_proj[tokens[(b0 + 2 * g + 1) * TN] * G4N + grow];
        }
    }

    float creg[2] = {0.f, 0.f}, hreg[2] = {0.f, 0.f};
    unsigned ph[2][2] = {{0u, 0u}, {0u, 0u}};   // [group][buf]

    for (int t = 0; t < steps; t++) {
        const int buf = t & 1;
        const int nb  = buf ^ 1;
#pragma unroll
        for (int g = 0; g < 2; g++) {
            // wait for this group's h(t) (skip t=0: buffers prezeroed)
            if (t) {
                unsigned p = buf ? ph[g][1] : ph[g][0];
                mbar_wait(smem_u32(&mbar[g][buf]), p);
                if (buf) ph[g][1] ^= 1u; else ph[g][0] ^= 1u;
            }
            // re-arm this group's barrier for step t+2
            if (tid == 0) mbar_arm(smem_u32(&mbar[g][buf]), TXB);

            // prefetch next step's input projection
            float xn0, xn1;
            if (q == 0) {
                int tn = min(t + 1, TN - 1);
                xn0 = g_proj[tokens[(b0 + 2 * g + 0) * TN + tn] * G4N + grow];
                xn1 = g_proj[tokens[(b0 + 2 * g + 1) * TN + tn] * G4N + grow];
            }

            // packed matvec: my gate row, my k-quarter, this group's 2 batches
            const float* h0p = hb[g][buf][0] + q * 64;
            const float* h1p = hb[g][buf][1] + q * 64;
            unsigned long long a0 = 0ull, a1 = 0ull;
#pragma unroll
            for (int c = 0; c < 16; c++) {
                ulonglong2 h0 = *(const ulonglong2*)(h0p + c * 4);
                ulonglong2 h1 = *(const ulonglong2*)(h1p + c * 4);
                a0 = fma2(wpair[2 * c],     h0.x, a0);
                a1 = fma2(wpair[2 * c],     h1.x, a1);
                a0 = fma2(wpair[2 * c + 1], h0.y, a0);
                a1 = fma2(wpair[2 * c + 1], h1.y, a1);
            }
            if (q == 0) {
                psum[g][0][0][lr] = lo32(a0) + hi32(a0) + xw[g][0];
                psum[g][0][1][lr] = lo32(a1) + hi32(a1) + xw[g][1];
                xw[g][0] = xn0; xw[g][1] = xn1;
            } else {
                psum[g][q][0][lr] = lo32(a0) + hi32(a0);
                psum[g][q][1][lr] = lo32(a1) + hi32(a1);
            }
            __syncthreads();

            // cell update on tid<128; other warps sail into the next half.
            if (tid < 128) {
                const int r0 = (s ? 64 : 0) + hl;
                const int r1 = (s ? 96 : 32) + hl;
                float gA = (psum[g][0][bb][r0] + psum[g][1][bb][r0]) +
                           (psum[g][2][bb][r0] + psum[g][3][bb][r0]);
                float gB = (psum[g][0][bb][r1] + psum[g][1][bb][r1]) +
                           (psum[g][2][bb][r1] + psum[g][3][bb][r1]);
                float u = s ? tanhf_(gA) : sigf(gA);
                float v = sigf(gB);
                float ou = __shfl_xor_sync(0xffffffffu, u, 1);
                float ov = __shfl_xor_sync(0xffffffffu, v, 1);
                float i_ = s ? ou : u;
                float f_ = s ? ov : v;
                float g_ = s ? u  : ou;
                float o_ = s ? v  : ov;
                float cn = f_ * creg[g] + i_ * g_;
                float hn = o_ * tanhf_(cn);
                if (t < mylen[g]) { creg[g] = cn; hreg[g] = hn; }

                if (t + 1 < steps) {
                    // fire-and-forget remote stores w/ completion tx
                    const unsigned dloc = smem_u32(&hb[g][nb][bb][base + hl]);
                    const unsigned mloc = smem_u32(&mbar[g][nb]);
#pragma unroll
                    for (int r = 0; r < 4; r++) {
                        const unsigned rk = 4 * s + r;
                        st_async_f32(mapa_u32(dloc, rk), hreg[g],
                                     mapa_u32(mloc, rk));
                    }
                }
            }
        }
    }

    if (tid < 128 && s == 0) {
        out[(b0 + 0 + bb) * HIDN + base + hl] = hreg[0];
        out[(b0 + 2 + bb) * HIDN + base + hl] = hreg[1];
    }
}

// ---------------------------------------------------------------------------
extern "C" void kernel_launch(void* const* d_in, const int* in_sizes, int n_in,
                              void* d_out, int out_size)
{
    const int*   tokens  = (const int*)d_in[0];
    const int*   lengths = (const int*)d_in[1];
    const float* emb     = (const float*)d_in[2];
    const float* W_ih    = (const float*)d_in[3];
    const float* W_hh    = (const float*)d_in[4];
    const float* b_ih    = (const float*)d_in[5];
    const float* b_hh    = (const float*)d_in[6];
    float* out = (float*)d_out;

    proj_kernel<<<VOCABN / 8, 256>>>(emb, W_ih, b_ih, b_hh);

    dim3 grid(CL, BN / 4);
    lstm_kernel<<<grid, NTH>>>(tokens, lengths, W_hh, out);
}